// round 13
// baseline (speedup 1.0000x reference)
#include <cuda_runtime.h>
#include <cuda_bf16.h>
#include <cstdint>

#define N_NODES 50000
#define N_EDGES 600000
#define D 128
#define EPS 1e-5f
#define NB_SCAN ((N_NODES + 1023) / 1024)
#define N_TILES ((N_NODES + 127) / 128)

typedef unsigned long long u64;

// ---------------- scratch (no allocations allowed) ----------------
// Invariant: g_count and g_bsum64 are zero at kernel_launch entry (static
// zero-init on first run; scan/hist restore them each run for graph replays).
__device__ __align__(16) float g_agg[N_NODES * D];
__device__ __align__(16) float g_h[N_NODES * D];
__device__ __align__(16) float g_colsum[D];
__device__ __align__(16) float g_colsq[D];
__device__ int g_count[N_NODES];
__device__ u64 g_bsum64[64];
__device__ int g_off[N_NODES + 1];
__device__ int g_rank[N_EDGES];
__device__ __align__(8) int2 g_pair[N_EDGES];  // {edge_id, src}

// per-block int64-vs-int32 edge_index detection (high words all zero => int64)
__device__ __forceinline__ int detect_idx64_block(const int* __restrict__ ei_raw,
                                                  int* s_flag) {
    if (threadIdx.x < 32) {
        int ok = 1;
        for (int k = threadIdx.x; k < 64; k += 32)
            if (ei_raw[2 * k + 1] != 0) ok = 0;
        ok = __all_sync(0xffffffffu, ok) ? 1 : 0;
        if (threadIdx.x == 0) *s_flag = ok;
    }
    __syncthreads();
    return *s_flag;
}

// ---------------- K0: histogram + per-edge rank (4-edge ILP) ----------------
__global__ void hist_kernel(const void* __restrict__ ei) {
    __shared__ int s_idx64;
    int i64 = detect_idx64_block((const int*)ei, &s_idx64);
    if (blockIdx.x == 0 && threadIdx.x < 64) g_bsum64[threadIdx.x] = 0ULL;
    int e0 = blockIdx.x * 1024 + threadIdx.x;
    int d[4];
#pragma unroll
    for (int j = 0; j < 4; j++) {
        int e = e0 + 256 * j;
        d[j] = -1;
        if (e < N_EDGES)
            d[j] = i64 ? (int)((const long long*)ei)[N_EDGES + e]
                       : ((const int*)ei)[N_EDGES + e];
    }
#pragma unroll
    for (int j = 0; j < 4; j++) {
        int e = e0 + 256 * j;
        if ((unsigned)d[j] < N_NODES)
            g_rank[e] = atomicAdd(&g_count[d[j]], 1);
    }
}

// ---------------- K1: single-pass scan (lookback), self-restoring -----------
__global__ void scan_kernel() {
    __shared__ int wsum[32];
    __shared__ int btot_sh;
    __shared__ int pref_sh[2];
    int t = threadIdx.x;
    int lane = t & 31;
    int wrp = t >> 5;
    int bid = blockIdx.x;
    int i = bid * 1024 + t;
    int v = (i < N_NODES) ? g_count[i] : 0;
    if (i < N_NODES) g_count[i] = 0;  // restore invariant for next replay
    if (bid == 0 && t < D) { g_colsum[t] = 0.f; g_colsq[t] = 0.f; }
    int s = v;
#pragma unroll
    for (int off = 1; off < 32; off <<= 1) {
        int u = __shfl_up_sync(0xffffffffu, s, off);
        if (lane >= off) s += u;
    }
    if (lane == 31) wsum[wrp] = s;
    __syncthreads();
    if (wrp == 0) {
        int w = wsum[lane];
#pragma unroll
        for (int off = 1; off < 32; off <<= 1) {
            int u = __shfl_up_sync(0xffffffffu, w, off);
            if (lane >= off) w += u;
        }
        wsum[lane] = w;
    }
    __syncthreads();
    int incl = s + (wrp > 0 ? wsum[wrp - 1] : 0);
    if (t == 1023) btot_sh = incl;
    __syncthreads();
    if (t == 0)
        atomicExch(&g_bsum64[bid], (1ULL << 40) | (u64)btot_sh);
    int p = 0;
    if (t < bid) {
        volatile u64* bs = (volatile u64*)g_bsum64;
        u64 x;
        do { x = bs[t]; } while (!(x >> 40));
        p = (int)(x & 0xFFFFFFFFFFULL);
    }
    if (t < 64) {
#pragma unroll
        for (int off = 16; off; off >>= 1)
            p += __shfl_xor_sync(0xffffffffu, p, off);
        if (lane == 0) pref_sh[wrp] = p;
    }
    __syncthreads();
    int prefix = pref_sh[0] + pref_sh[1];
    if (i < N_NODES) g_off[i] = incl - v + prefix;
    if (i == 0) g_off[N_NODES] = N_EDGES;
}

// ---------------- K2: fill (atomic-free, 4-edge ILP) ------------------------
__global__ void fill_kernel(const void* __restrict__ ei) {
    __shared__ int s_idx64;
    int i64 = detect_idx64_block((const int*)ei, &s_idx64);
    int e0 = blockIdx.x * 1024 + threadIdx.x;
#pragma unroll
    for (int j = 0; j < 4; j++) {
        int e = e0 + 256 * j;
        if (e >= N_EDGES) break;
        int d, s;
        if (i64) {
            const long long* e64 = (const long long*)ei;
            s = (int)e64[e];
            d = (int)e64[N_EDGES + e];
        } else {
            const int* e32 = (const int*)ei;
            s = e32[e];
            d = e32[N_EDGES + e];
        }
        if ((unsigned)d >= N_NODES) continue;
        int pos = g_off[d] + g_rank[e];
        g_pair[pos] = make_int2(e, s);
    }
}

// ---------------- K3: gather aggregation (one warp per node) ----------------
__global__ void __launch_bounds__(256) gather_kernel(
    const float* __restrict__ node, const float* __restrict__ edge) {
    int w = (blockIdx.x * blockDim.x + threadIdx.x) >> 5;
    int lane = threadIdx.x & 31;
    if (w >= N_NODES) return;
    int beg = g_off[w], end = g_off[w + 1];
    const float4* n4 = (const float4*)node;
    const float4* e4 = (const float4*)edge;
    float4 acc0 = make_float4(0.f, 0.f, 0.f, 0.f);
    float4 acc1 = make_float4(0.f, 0.f, 0.f, 0.f);
    int i = beg;
    for (; i + 2 <= end; i += 2) {
        int2 p0 = g_pair[i];
        int2 p1 = g_pair[i + 1];
        bool v0 = (unsigned)p0.y < N_NODES;
        bool v1 = (unsigned)p1.y < N_NODES;
        float4 a0, b0, a1, b1;
        if (v0) {
            a0 = n4[(size_t)p0.y * (D / 4) + lane];
            b0 = __ldcs(&e4[(size_t)p0.x * (D / 4) + lane]);
        }
        if (v1) {
            a1 = n4[(size_t)p1.y * (D / 4) + lane];
            b1 = __ldcs(&e4[(size_t)p1.x * (D / 4) + lane]);
        }
        if (v0) {
            acc0.x += a0.x + b0.x; acc0.y += a0.y + b0.y;
            acc0.z += a0.z + b0.z; acc0.w += a0.w + b0.w;
        }
        if (v1) {
            acc1.x += a1.x + b1.x; acc1.y += a1.y + b1.y;
            acc1.z += a1.z + b1.z; acc1.w += a1.w + b1.w;
        }
    }
    if (i < end) {
        int2 p = g_pair[i];
        if ((unsigned)p.y < N_NODES) {
            float4 a = n4[(size_t)p.y * (D / 4) + lane];
            float4 b = __ldcs(&e4[(size_t)p.x * (D / 4) + lane]);
            acc0.x += a.x + b.x; acc0.y += a.y + b.y;
            acc0.z += a.z + b.z; acc0.w += a.w + b.w;
        }
    }
    acc0.x += acc1.x; acc0.y += acc1.y; acc0.z += acc1.z; acc0.w += acc1.w;
    ((float4*)g_agg)[(size_t)w * (D / 4) + lane] = acc0;
}

// ================= K4: MLP via mma.sync bf16 + fused colstats ===============
#define SM_A_HI 0
#define SM_A_LO 32768
#define SM_W_HI 65536
#define SM_W_LO 98304
#define SM_MISC 131072
#define SM_B1 (SM_MISC + 0)
#define SM_B2 (SM_MISC + 512)
#define SM_LNG (SM_MISC + 1024)
#define SM_LNB (SM_MISC + 1536)
#define SM_CS (SM_MISC + 2048)
#define SM_CQ (SM_MISC + 2560)
#define MLP_SMEM_BYTES (SM_MISC + 3072)

__device__ __forceinline__ uint32_t swz(int row, int col) {
    uint32_t b = (uint32_t)(col << 1);
    return ((uint32_t)row << 8) + ((b & 0x7Fu) ^ (((uint32_t)(row & 7)) << 4)) +
           (b & 0x80u);
}
__device__ __forceinline__ uint32_t smem_u32(const void* p) {
    uint32_t a;
    asm("{ .reg .u64 t; cvta.to.shared.u64 t, %1; cvt.u32.u64 %0, t; }"
        : "=r"(a) : "l"(p));
    return a;
}
__device__ __forceinline__ uint32_t pack_bf(float a, float b) {
    unsigned short lo = __bfloat16_as_ushort(__float2bfloat16_rn(a));
    unsigned short hi = __bfloat16_as_ushort(__float2bfloat16_rn(b));
    return (uint32_t)lo | ((uint32_t)hi << 16);
}
__device__ __forceinline__ void ldsm_x4(uint32_t addr, uint32_t r[4]) {
    asm volatile(
        "ldmatrix.sync.aligned.m8n8.x4.shared.b16 {%0,%1,%2,%3}, [%4];"
        : "=r"(r[0]), "=r"(r[1]), "=r"(r[2]), "=r"(r[3]) : "r"(addr));
}
__device__ __forceinline__ void ldsm_x4_t(uint32_t addr, uint32_t r[4]) {
    asm volatile(
        "ldmatrix.sync.aligned.m8n8.x4.trans.shared.b16 {%0,%1,%2,%3}, [%4];"
        : "=r"(r[0]), "=r"(r[1]), "=r"(r[2]), "=r"(r[3]) : "r"(addr));
}
__device__ __forceinline__ void mma16816(float d[4], const uint32_t a[4],
                                         uint32_t b0, uint32_t b1) {
    asm volatile(
        "mma.sync.aligned.m16n8k16.row.col.f32.bf16.bf16.f32 "
        "{%0,%1,%2,%3}, {%4,%5,%6,%7}, {%8,%9}, {%0,%1,%2,%3};"
        : "+f"(d[0]), "+f"(d[1]), "+f"(d[2]), "+f"(d[3])
        : "r"(a[0]), "r"(a[1]), "r"(a[2]), "r"(a[3]), "r"(b0), "r"(b1));
}

__device__ __forceinline__ void gemm128(uint32_t aHi, uint32_t aLo,
                                        uint32_t wHi, uint32_t wLo,
                                        int mbase, int lane, float acc[16][4]) {
    const int m = lane >> 3, rr = lane & 7;
    const int arow = mbase + (m & 1) * 8 + rr;
    const int acol = (m >> 1) * 8;
    const int brow = (m & 1) * 8 + rr;
    const int bcol = (m >> 1) * 8;
#pragma unroll
    for (int nt = 0; nt < 16; nt++)
#pragma unroll
        for (int i = 0; i < 4; i++) acc[nt][i] = 0.f;
#pragma unroll
    for (int kc = 0; kc < 8; kc++) {
        uint32_t ah[4], al[4];
        uint32_t aoff = swz(arow, kc * 16 + acol);
        ldsm_x4(aHi + aoff, ah);
        ldsm_x4(aLo + aoff, al);
#pragma unroll
        for (int ntp = 0; ntp < 8; ntp++) {
            uint32_t bh[4], bl[4];
            uint32_t boff = swz(kc * 16 + brow, ntp * 16 + bcol);
            ldsm_x4_t(wHi + boff, bh);
            ldsm_x4_t(wLo + boff, bl);
            mma16816(acc[2 * ntp], ah, bh[0], bh[1]);
            mma16816(acc[2 * ntp], al, bh[0], bh[1]);
            mma16816(acc[2 * ntp], ah, bl[0], bl[1]);
            mma16816(acc[2 * ntp + 1], ah, bh[2], bh[3]);
            mma16816(acc[2 * ntp + 1], al, bh[2], bh[3]);
            mma16816(acc[2 * ntp + 1], ah, bl[2], bl[3]);
        }
    }
}

__device__ __forceinline__ void load_w(char* sm, const float* __restrict__ w,
                                       int tid) {
    const int k = tid >> 1;
    const int nbase = (tid & 1) * 64;
#pragma unroll 4
    for (int j = 0; j < 16; j++) {
        int n = nbase + 4 * j;
        float4 v = *(const float4*)(w + (size_t)k * D + n);
        float hx = __bfloat162float(__float2bfloat16_rn(v.x));
        float hy = __bfloat162float(__float2bfloat16_rn(v.y));
        float hz = __bfloat162float(__float2bfloat16_rn(v.z));
        float hw = __bfloat162float(__float2bfloat16_rn(v.w));
        uint32_t off = swz(k, n);
        *(uint2*)(sm + SM_W_HI + off) = make_uint2(pack_bf(v.x, v.y), pack_bf(v.z, v.w));
        *(uint2*)(sm + SM_W_LO + off) =
            make_uint2(pack_bf(v.x - hx, v.y - hy), pack_bf(v.z - hz, v.w - hw));
    }
}

__global__ void __launch_bounds__(256, 1)
mlp_mma_kernel(const float* __restrict__ w1, const float* __restrict__ b1,
               const float* __restrict__ w2, const float* __restrict__ b2,
               const float* __restrict__ lng, const float* __restrict__ lnb) {
    extern __shared__ __align__(16) char sm[];
    const uint32_t smb = smem_u32(sm);
    const int tid = threadIdx.x;
    const int wid = tid >> 5;
    const int lane = tid & 31;
    const int mbase = wid * 16;
    const int rowbase = blockIdx.x * 128;

    float* b1s = (float*)(sm + SM_B1);
    float* b2s = (float*)(sm + SM_B2);
    float* gs = (float*)(sm + SM_LNG);
    float* bs = (float*)(sm + SM_LNB);
    float* s_cs = (float*)(sm + SM_CS);
    float* s_cq = (float*)(sm + SM_CQ);
    if (tid < D) {
        b1s[tid] = b1[tid];
        b2s[tid] = b2[tid];
        gs[tid] = lng[tid];
        bs[tid] = lnb[tid];
        s_cs[tid] = 0.f;
        s_cq[tid] = 0.f;
    }

    load_w(sm, w1, tid);

#pragma unroll 4
    for (int i = 0; i < 16; i++) {
        int row = mbase + i;
        int gr = rowbase + row;
        float4 v = make_float4(0.f, 0.f, 0.f, 0.f);
        if (gr < N_NODES) v = *(const float4*)(g_agg + (size_t)gr * D + 4 * lane);
        float hx = __bfloat162float(__float2bfloat16_rn(v.x));
        float hy = __bfloat162float(__float2bfloat16_rn(v.y));
        float hz = __bfloat162float(__float2bfloat16_rn(v.z));
        float hw = __bfloat162float(__float2bfloat16_rn(v.w));
        uint32_t off = swz(row, 4 * lane);
        *(uint2*)(sm + SM_A_HI + off) = make_uint2(pack_bf(v.x, v.y), pack_bf(v.z, v.w));
        *(uint2*)(sm + SM_A_LO + off) =
            make_uint2(pack_bf(v.x - hx, v.y - hy), pack_bf(v.z - hz, v.w - hw));
    }
    __syncthreads();

    float acc[16][4];
    gemm128(smb + SM_A_HI, smb + SM_A_LO, smb + SM_W_HI, smb + SM_W_LO,
            mbase, lane, acc);
    __syncthreads();

    // epilogue 1: bias + ReLU + bf16 hi/lo split back into A buffers
    {
        const int g = lane >> 2, q = lane & 3;
        const int r0 = mbase + g, r1 = r0 + 8;
#pragma unroll
        for (int nt = 0; nt < 16; nt++) {
            int c = nt * 8 + 2 * q;
            float bb0 = b1s[c], bb1 = b1s[c + 1];
            float v0 = fmaxf(acc[nt][0] + bb0, 0.f);
            float v1 = fmaxf(acc[nt][1] + bb1, 0.f);
            float v2 = fmaxf(acc[nt][2] + bb0, 0.f);
            float v3 = fmaxf(acc[nt][3] + bb1, 0.f);
            float h0 = __bfloat162float(__float2bfloat16_rn(v0));
            float h1 = __bfloat162float(__float2bfloat16_rn(v1));
            float h2 = __bfloat162float(__float2bfloat16_rn(v2));
            float h3 = __bfloat162float(__float2bfloat16_rn(v3));
            uint32_t o0 = swz(r0, c), o1 = swz(r1, c);
            *(uint32_t*)(sm + SM_A_HI + o0) = pack_bf(v0, v1);
            *(uint32_t*)(sm + SM_A_LO + o0) = pack_bf(v0 - h0, v1 - h1);
            *(uint32_t*)(sm + SM_A_HI + o1) = pack_bf(v2, v3);
            *(uint32_t*)(sm + SM_A_LO + o1) = pack_bf(v2 - h2, v3 - h3);
        }
    }
    load_w(sm, w2, tid);
    __syncthreads();

    gemm128(smb + SM_A_HI, smb + SM_A_LO, smb + SM_W_HI, smb + SM_W_LO,
            mbase, lane, acc);

    // epilogue 2: bias + LayerNorm + store g_h + fused column stats
    {
        const int g = lane >> 2, q = lane & 3;
        const int r0 = mbase + g, r1 = r0 + 8;
        float s0 = 0.f, q0 = 0.f, s1 = 0.f, q1 = 0.f;
#pragma unroll
        for (int nt = 0; nt < 16; nt++) {
            int c = nt * 8 + 2 * q;
            float bb0 = b2s[c], bb1 = b2s[c + 1];
            acc[nt][0] += bb0;
            acc[nt][1] += bb1;
            acc[nt][2] += bb0;
            acc[nt][3] += bb1;
            s0 += acc[nt][0] + acc[nt][1];
            q0 += acc[nt][0] * acc[nt][0] + acc[nt][1] * acc[nt][1];
            s1 += acc[nt][2] + acc[nt][3];
            q1 += acc[nt][2] * acc[nt][2] + acc[nt][3] * acc[nt][3];
        }
#pragma unroll
        for (int off = 1; off < 4; off <<= 1) {
            s0 += __shfl_xor_sync(0xffffffffu, s0, off);
            q0 += __shfl_xor_sync(0xffffffffu, q0, off);
            s1 += __shfl_xor_sync(0xffffffffu, s1, off);
            q1 += __shfl_xor_sync(0xffffffffu, q1, off);
        }
        const float invD = 1.f / D;
        float mu0 = s0 * invD, mu1 = s1 * invD;
        float rs0 = rsqrtf(q0 * invD - mu0 * mu0 + EPS);
        float rs1 = rsqrtf(q1 * invD - mu1 * mu1 + EPS);
        int gr0 = rowbase + r0, gr1 = rowbase + r1;
        bool ok0 = gr0 < N_NODES, ok1 = gr1 < N_NODES;
#pragma unroll
        for (int nt = 0; nt < 16; nt++) {
            int c = nt * 8 + 2 * q;
            float gg0 = gs[c], gg1 = gs[c + 1];
            float be0 = bs[c], be1 = bs[c + 1];
            float y00 = 0.f, y01 = 0.f, y10 = 0.f, y11 = 0.f;
            if (ok0) {
                y00 = fmaf((acc[nt][0] - mu0) * rs0, gg0, be0);
                y01 = fmaf((acc[nt][1] - mu0) * rs0, gg1, be1);
                *(float2*)(g_h + (size_t)gr0 * D + c) = make_float2(y00, y01);
            }
            if (ok1) {
                y10 = fmaf((acc[nt][2] - mu1) * rs1, gg0, be0);
                y11 = fmaf((acc[nt][3] - mu1) * rs1, gg1, be1);
                *(float2*)(g_h + (size_t)gr1 * D + c) = make_float2(y10, y11);
            }
            float sc = y00 + y10, sc1 = y01 + y11;
            float qc = y00 * y00 + y10 * y10, qc1 = y01 * y01 + y11 * y11;
#pragma unroll
            for (int off = 4; off < 32; off <<= 1) {
                sc += __shfl_xor_sync(0xffffffffu, sc, off);
                sc1 += __shfl_xor_sync(0xffffffffu, sc1, off);
                qc += __shfl_xor_sync(0xffffffffu, qc, off);
                qc1 += __shfl_xor_sync(0xffffffffu, qc1, off);
            }
            if (lane < 4) {
                atomicAdd(&s_cs[c], sc);
                atomicAdd(&s_cs[c + 1], sc1);
                atomicAdd(&s_cq[c], qc);
                atomicAdd(&s_cq[c + 1], qc1);
            }
        }
    }
    __syncthreads();
    if (tid < D) {
        atomicAdd(&g_colsum[tid], s_cs[tid]);
        atomicAdd(&g_colsq[tid], s_cq[tid]);
    }
}

// ---------------- K5: GraphNorm stats + apply + ReLU + residual -------------
__global__ void __launch_bounds__(256) final_kernel(
    const float* __restrict__ node, const float* __restrict__ gn_w,
    const float* __restrict__ gn_b, const float* __restrict__ gn_ms,
    float* __restrict__ out) {
    __shared__ float s_scale[D];
    __shared__ float s_shift[D];
    if (threadIdx.x < D) {
        int j = threadIdx.x;
        const float invN = 1.f / (float)N_NODES;
        float mu = g_colsum[j] * invN;
        float ex2 = g_colsq[j] * invN;
        float ms = gn_ms[j];
        float var = ex2 - 2.f * ms * mu * mu + ms * ms * mu * mu;
        float a = rsqrtf(var + EPS) * gn_w[j];
        s_scale[j] = a;
        s_shift[j] = gn_b[j] - ms * mu * a;
    }
    __syncthreads();
    int i = blockIdx.x * blockDim.x + threadIdx.x;
    const int tot4 = N_NODES * D / 4;
    if (i >= tot4) return;
    const float4* h4 = (const float4*)g_h;
    const float4* n4 = (const float4*)node;
    const float4* s4 = (const float4*)s_scale;
    const float4* t4 = (const float4*)s_shift;
    float4* o4 = (float4*)out;
    int c = i & 31;
    float4 h = h4[i], s = s4[c], t = t4[c], n = n4[i];
    float4 r;
    r.x = fmaxf(fmaf(h.x, s.x, t.x), 0.f) + n.x;
    r.y = fmaxf(fmaf(h.y, s.y, t.y), 0.f) + n.y;
    r.z = fmaxf(fmaf(h.z, s.z, t.z), 0.f) + n.z;
    r.w = fmaxf(fmaf(h.w, s.w, t.w), 0.f) + n.w;
    o4[i] = r;
}

// ---------------- launch ----------------
extern "C" void kernel_launch(void* const* d_in, const int* in_sizes, int n_in,
                              void* d_out, int out_size) {
    const float* node = (const float*)d_in[0];
    const float* edge = (const float*)d_in[1];
    const float* w1 = (const float*)d_in[2];
    const float* b1 = (const float*)d_in[3];
    const float* w2 = (const float*)d_in[4];
    const float* b2 = (const float*)d_in[5];
    const float* lng = (const float*)d_in[6];
    const float* lnb = (const float*)d_in[7];
    const float* gnw = (const float*)d_in[8];
    const float* gnb = (const float*)d_in[9];
    const float* gnms = (const float*)d_in[10];
    const void* ei = d_in[11];
    float* out = (float*)d_out;

    static int inited = 0;
    if (!inited) {
        inited = 1;
        cudaFuncSetAttribute(mlp_mma_kernel,
                             cudaFuncAttributeMaxDynamicSharedMemorySize,
                             MLP_SMEM_BYTES);
    }

    const int edge_blocks = (N_EDGES + 1023) / 1024;
    hist_kernel<<<edge_blocks, 256>>>(ei);
    scan_kernel<<<NB_SCAN, 1024>>>();
    fill_kernel<<<edge_blocks, 256>>>(ei);

    const int gather_blocks = (N_NODES * 32 + 255) / 256;
    gather_kernel<<<gather_blocks, 256>>>(node, edge);

    mlp_mma_kernel<<<N_TILES, 256, MLP_SMEM_BYTES>>>(w1, b1, w2, b2, lng, lnb);

    const int tot4 = N_NODES * D / 4;
    final_kernel<<<(tot4 + 255) / 256, 256>>>(node, gnw, gnb, gnms, out);
}

// round 15
// speedup vs baseline: 1.3355x; 1.3355x over previous
#include <cuda_runtime.h>
#include <cuda_bf16.h>
#include <cstdint>

#define N_NODES 50000
#define N_EDGES 600000
#define D 128
#define EPS 1e-5f
#define NB_SCAN ((N_NODES + 1023) / 1024)
#define N_TILES ((N_NODES + 127) / 128)

typedef unsigned long long u64;

// ---------------- scratch (no allocations allowed) ----------------
__device__ __align__(16) float g_agg[N_NODES * D];
__device__ __align__(16) float g_h[N_NODES * D];
__device__ __align__(16) float g_colsum[D];
__device__ __align__(16) float g_colsq[D];
__device__ int g_count[N_NODES];
__device__ u64 g_bsum64[64];
__device__ int g_off[N_NODES + 1];
__device__ int g_cursor[N_NODES];
__device__ __align__(8) int2 g_pair[N_EDGES];  // {edge_id, src}
__device__ int g_idx64;

// ---------------- K0: zero counters + colstats + detect idx dtype -----------
__global__ void zero_kernel(const int* __restrict__ ei_raw) {
    int i = blockIdx.x * blockDim.x + threadIdx.x;
    if (i < N_NODES) g_count[i] = 0;
    if (i < D) { g_colsum[i] = 0.f; g_colsq[i] = 0.f; }
    if (i < 64) g_bsum64[i] = 0ULL;
    if (blockIdx.x == 0 && threadIdx.x < 32) {
        int ok = 1;
        for (int k = threadIdx.x; k < 64; k += 32)
            if (ei_raw[2 * k + 1] != 0) ok = 0;
        ok = __all_sync(0xffffffffu, ok) ? 1 : 0;
        if (threadIdx.x == 0) g_idx64 = ok;
    }
}

// ---------------- CSR build ----------------
__global__ void hist_kernel(const void* __restrict__ ei) {
    int e = blockIdx.x * blockDim.x + threadIdx.x;
    if (e >= N_EDGES) return;
    int d = g_idx64 ? (int)((const long long*)ei)[N_EDGES + e]
                    : ((const int*)ei)[N_EDGES + e];
    if ((unsigned)d < N_NODES) atomicAdd(&g_count[d], 1);  // result unused -> REDG
}

// single-pass scan: local block scan + lookback over published block sums.
__global__ void scan_kernel() {
    __shared__ int wsum[32];
    __shared__ int btot_sh;
    __shared__ int pref_sh[2];
    int t = threadIdx.x;
    int lane = t & 31;
    int wrp = t >> 5;
    int bid = blockIdx.x;
    int i = bid * 1024 + t;
    int v = (i < N_NODES) ? g_count[i] : 0;
    int s = v;
#pragma unroll
    for (int off = 1; off < 32; off <<= 1) {
        int u = __shfl_up_sync(0xffffffffu, s, off);
        if (lane >= off) s += u;
    }
    if (lane == 31) wsum[wrp] = s;
    __syncthreads();
    if (wrp == 0) {
        int w = wsum[lane];
#pragma unroll
        for (int off = 1; off < 32; off <<= 1) {
            int u = __shfl_up_sync(0xffffffffu, w, off);
            if (lane >= off) w += u;
        }
        wsum[lane] = w;
    }
    __syncthreads();
    int incl = s + (wrp > 0 ? wsum[wrp - 1] : 0);
    if (t == 1023) btot_sh = incl;
    __syncthreads();
    if (t == 0)
        atomicExch(&g_bsum64[bid], (1ULL << 40) | (u64)btot_sh);
    int p = 0;
    if (t < bid) {
        volatile u64* bs = (volatile u64*)g_bsum64;
        u64 x;
        do { x = bs[t]; } while (!(x >> 40));
        p = (int)(x & 0xFFFFFFFFFFULL);
    }
    if (t < 64) {
#pragma unroll
        for (int off = 16; off; off >>= 1)
            p += __shfl_xor_sync(0xffffffffu, p, off);
        if (lane == 0) pref_sh[wrp] = p;
    }
    __syncthreads();
    int prefix = pref_sh[0] + pref_sh[1];
    if (i < N_NODES) {
        int o = incl - v + prefix;
        g_off[i] = o;
        g_cursor[i] = o;
    }
    if (i == 0) g_off[N_NODES] = N_EDGES;
}

__global__ void fill_kernel(const void* __restrict__ ei) {
    int e = blockIdx.x * blockDim.x + threadIdx.x;
    if (e >= N_EDGES) return;
    int d, s;
    if (g_idx64) {
        const long long* e64 = (const long long*)ei;
        s = (int)e64[e];
        d = (int)e64[N_EDGES + e];
    } else {
        const int* e32 = (const int*)ei;
        s = e32[e];
        d = e32[N_EDGES + e];
    }
    if ((unsigned)d >= N_NODES) return;
    int pos = atomicAdd(&g_cursor[d], 1);
    g_pair[pos] = make_int2(e, s);
}

// ---------------- K1: gather (warp/node, coalesced pair prefetch + shfl) ----
__global__ void __launch_bounds__(256) gather_kernel(
    const float* __restrict__ node, const float* __restrict__ edge) {
    int w = (blockIdx.x * blockDim.x + threadIdx.x) >> 5;
    int lane = threadIdx.x & 31;
    if (w >= N_NODES) return;
    int beg = g_off[w], end = g_off[w + 1];
    const float4* n4 = (const float4*)node;
    const float4* e4 = (const float4*)edge;
    float4 acc0 = make_float4(0.f, 0.f, 0.f, 0.f);
    float4 acc1 = make_float4(0.f, 0.f, 0.f, 0.f);
    for (int base = beg; base < end; base += 32) {
        int cnt = end - base;
        if (cnt > 32) cnt = 32;
        // one coalesced per-lane load grabs up to 32 {edge,src} pairs
        int2 p = make_int2(0, -1);
        if (lane < cnt) p = g_pair[base + lane];
        int j = 0;
        for (; j + 2 <= cnt; j += 2) {
            int e0 = __shfl_sync(0xffffffffu, p.x, j);
            int s0 = __shfl_sync(0xffffffffu, p.y, j);
            int e1 = __shfl_sync(0xffffffffu, p.x, j + 1);
            int s1 = __shfl_sync(0xffffffffu, p.y, j + 1);
            bool v0 = (unsigned)s0 < N_NODES;
            bool v1 = (unsigned)s1 < N_NODES;
            float4 a0, b0, a1, b1;
            if (v0) {
                a0 = n4[(size_t)s0 * (D / 4) + lane];
                b0 = __ldcs(&e4[(size_t)e0 * (D / 4) + lane]);
            }
            if (v1) {
                a1 = n4[(size_t)s1 * (D / 4) + lane];
                b1 = __ldcs(&e4[(size_t)e1 * (D / 4) + lane]);
            }
            if (v0) {
                acc0.x += a0.x + b0.x; acc0.y += a0.y + b0.y;
                acc0.z += a0.z + b0.z; acc0.w += a0.w + b0.w;
            }
            if (v1) {
                acc1.x += a1.x + b1.x; acc1.y += a1.y + b1.y;
                acc1.z += a1.z + b1.z; acc1.w += a1.w + b1.w;
            }
        }
        if (j < cnt) {
            int e0 = __shfl_sync(0xffffffffu, p.x, j);
            int s0 = __shfl_sync(0xffffffffu, p.y, j);
            if ((unsigned)s0 < N_NODES) {
                float4 a = n4[(size_t)s0 * (D / 4) + lane];
                float4 b = __ldcs(&e4[(size_t)e0 * (D / 4) + lane]);
                acc0.x += a.x + b.x; acc0.y += a.y + b.y;
                acc0.z += a.z + b.z; acc0.w += a.w + b.w;
            }
        }
    }
    acc0.x += acc1.x; acc0.y += acc1.y; acc0.z += acc1.z; acc0.w += acc1.w;
    ((float4*)g_agg)[(size_t)w * (D / 4) + lane] = acc0;
}

// ================= K2: MLP via mma.sync bf16 + fused colstats ===============
#define SM_A_HI 0
#define SM_A_LO 32768
#define SM_W_HI 65536
#define SM_W_LO 98304
#define SM_MISC 131072
#define SM_B1 (SM_MISC + 0)
#define SM_B2 (SM_MISC + 512)
#define SM_LNG (SM_MISC + 1024)
#define SM_LNB (SM_MISC + 1536)
#define SM_CS (SM_MISC + 2048)
#define SM_CQ (SM_MISC + 2560)
#define MLP_SMEM_BYTES (SM_MISC + 3072)

__device__ __forceinline__ uint32_t swz(int row, int col) {
    uint32_t b = (uint32_t)(col << 1);
    return ((uint32_t)row << 8) + ((b & 0x7Fu) ^ (((uint32_t)(row & 7)) << 4)) +
           (b & 0x80u);
}
__device__ __forceinline__ uint32_t smem_u32(const void* p) {
    uint32_t a;
    asm("{ .reg .u64 t; cvta.to.shared.u64 t, %1; cvt.u32.u64 %0, t; }"
        : "=r"(a) : "l"(p));
    return a;
}
__device__ __forceinline__ uint32_t pack_bf(float a, float b) {
    unsigned short lo = __bfloat16_as_ushort(__float2bfloat16_rn(a));
    unsigned short hi = __bfloat16_as_ushort(__float2bfloat16_rn(b));
    return (uint32_t)lo | ((uint32_t)hi << 16);
}
__device__ __forceinline__ void ldsm_x4(uint32_t addr, uint32_t r[4]) {
    asm volatile(
        "ldmatrix.sync.aligned.m8n8.x4.shared.b16 {%0,%1,%2,%3}, [%4];"
        : "=r"(r[0]), "=r"(r[1]), "=r"(r[2]), "=r"(r[3]) : "r"(addr));
}
__device__ __forceinline__ void ldsm_x4_t(uint32_t addr, uint32_t r[4]) {
    asm volatile(
        "ldmatrix.sync.aligned.m8n8.x4.trans.shared.b16 {%0,%1,%2,%3}, [%4];"
        : "=r"(r[0]), "=r"(r[1]), "=r"(r[2]), "=r"(r[3]) : "r"(addr));
}
__device__ __forceinline__ void mma16816(float d[4], const uint32_t a[4],
                                         uint32_t b0, uint32_t b1) {
    asm volatile(
        "mma.sync.aligned.m16n8k16.row.col.f32.bf16.bf16.f32 "
        "{%0,%1,%2,%3}, {%4,%5,%6,%7}, {%8,%9}, {%0,%1,%2,%3};"
        : "+f"(d[0]), "+f"(d[1]), "+f"(d[2]), "+f"(d[3])
        : "r"(a[0]), "r"(a[1]), "r"(a[2]), "r"(a[3]), "r"(b0), "r"(b1));
}

__device__ __forceinline__ void gemm128(uint32_t aHi, uint32_t aLo,
                                        uint32_t wHi, uint32_t wLo,
                                        int mbase, int lane, float acc[16][4]) {
    const int m = lane >> 3, rr = lane & 7;
    const int arow = mbase + (m & 1) * 8 + rr;
    const int acol = (m >> 1) * 8;
    const int brow = (m & 1) * 8 + rr;
    const int bcol = (m >> 1) * 8;
#pragma unroll
    for (int nt = 0; nt < 16; nt++)
#pragma unroll
        for (int i = 0; i < 4; i++) acc[nt][i] = 0.f;
#pragma unroll
    for (int kc = 0; kc < 8; kc++) {
        uint32_t ah[4], al[4];
        uint32_t aoff = swz(arow, kc * 16 + acol);
        ldsm_x4(aHi + aoff, ah);
        ldsm_x4(aLo + aoff, al);
#pragma unroll
        for (int ntp = 0; ntp < 8; ntp++) {
            uint32_t bh[4], bl[4];
            uint32_t boff = swz(kc * 16 + brow, ntp * 16 + bcol);
            ldsm_x4_t(wHi + boff, bh);
            ldsm_x4_t(wLo + boff, bl);
            mma16816(acc[2 * ntp], ah, bh[0], bh[1]);
            mma16816(acc[2 * ntp], al, bh[0], bh[1]);
            mma16816(acc[2 * ntp], ah, bl[0], bl[1]);
            mma16816(acc[2 * ntp + 1], ah, bh[2], bh[3]);
            mma16816(acc[2 * ntp + 1], al, bh[2], bh[3]);
            mma16816(acc[2 * ntp + 1], ah, bl[2], bl[3]);
        }
    }
}

__device__ __forceinline__ void load_w(char* sm, const float* __restrict__ w,
                                       int tid) {
    const int k = tid >> 1;
    const int nbase = (tid & 1) * 64;
#pragma unroll 4
    for (int j = 0; j < 16; j++) {
        int n = nbase + 4 * j;
        float4 v = *(const float4*)(w + (size_t)k * D + n);
        float hx = __bfloat162float(__float2bfloat16_rn(v.x));
        float hy = __bfloat162float(__float2bfloat16_rn(v.y));
        float hz = __bfloat162float(__float2bfloat16_rn(v.z));
        float hw = __bfloat162float(__float2bfloat16_rn(v.w));
        uint32_t off = swz(k, n);
        *(uint2*)(sm + SM_W_HI + off) = make_uint2(pack_bf(v.x, v.y), pack_bf(v.z, v.w));
        *(uint2*)(sm + SM_W_LO + off) =
            make_uint2(pack_bf(v.x - hx, v.y - hy), pack_bf(v.z - hz, v.w - hw));
    }
}

__global__ void __launch_bounds__(256, 1)
mlp_mma_kernel(const float* __restrict__ w1, const float* __restrict__ b1,
               const float* __restrict__ w2, const float* __restrict__ b2,
               const float* __restrict__ lng, const float* __restrict__ lnb) {
    extern __shared__ __align__(16) char sm[];
    const uint32_t smb = smem_u32(sm);
    const int tid = threadIdx.x;
    const int wid = tid >> 5;
    const int lane = tid & 31;
    const int mbase = wid * 16;
    const int rowbase = blockIdx.x * 128;

    float* b1s = (float*)(sm + SM_B1);
    float* b2s = (float*)(sm + SM_B2);
    float* gs = (float*)(sm + SM_LNG);
    float* bs = (float*)(sm + SM_LNB);
    float* s_cs = (float*)(sm + SM_CS);
    float* s_cq = (float*)(sm + SM_CQ);
    if (tid < D) {
        b1s[tid] = b1[tid];
        b2s[tid] = b2[tid];
        gs[tid] = lng[tid];
        bs[tid] = lnb[tid];
        s_cs[tid] = 0.f;
        s_cq[tid] = 0.f;
    }

    load_w(sm, w1, tid);

#pragma unroll 4
    for (int i = 0; i < 16; i++) {
        int row = mbase + i;
        int gr = rowbase + row;
        float4 v = make_float4(0.f, 0.f, 0.f, 0.f);
        if (gr < N_NODES) v = *(const float4*)(g_agg + (size_t)gr * D + 4 * lane);
        float hx = __bfloat162float(__float2bfloat16_rn(v.x));
        float hy = __bfloat162float(__float2bfloat16_rn(v.y));
        float hz = __bfloat162float(__float2bfloat16_rn(v.z));
        float hw = __bfloat162float(__float2bfloat16_rn(v.w));
        uint32_t off = swz(row, 4 * lane);
        *(uint2*)(sm + SM_A_HI + off) = make_uint2(pack_bf(v.x, v.y), pack_bf(v.z, v.w));
        *(uint2*)(sm + SM_A_LO + off) =
            make_uint2(pack_bf(v.x - hx, v.y - hy), pack_bf(v.z - hz, v.w - hw));
    }
    __syncthreads();

    float acc[16][4];
    gemm128(smb + SM_A_HI, smb + SM_A_LO, smb + SM_W_HI, smb + SM_W_LO,
            mbase, lane, acc);
    __syncthreads();

    // epilogue 1: bias + ReLU + bf16 hi/lo split back into A buffers
    {
        const int g = lane >> 2, q = lane & 3;
        const int r0 = mbase + g, r1 = r0 + 8;
#pragma unroll
        for (int nt = 0; nt < 16; nt++) {
            int c = nt * 8 + 2 * q;
            float bb0 = b1s[c], bb1 = b1s[c + 1];
            float v0 = fmaxf(acc[nt][0] + bb0, 0.f);
            float v1 = fmaxf(acc[nt][1] + bb1, 0.f);
            float v2 = fmaxf(acc[nt][2] + bb0, 0.f);
            float v3 = fmaxf(acc[nt][3] + bb1, 0.f);
            float h0 = __bfloat162float(__float2bfloat16_rn(v0));
            float h1 = __bfloat162float(__float2bfloat16_rn(v1));
            float h2 = __bfloat162float(__float2bfloat16_rn(v2));
            float h3 = __bfloat162float(__float2bfloat16_rn(v3));
            uint32_t o0 = swz(r0, c), o1 = swz(r1, c);
            *(uint32_t*)(sm + SM_A_HI + o0) = pack_bf(v0, v1);
            *(uint32_t*)(sm + SM_A_LO + o0) = pack_bf(v0 - h0, v1 - h1);
            *(uint32_t*)(sm + SM_A_HI + o1) = pack_bf(v2, v3);
            *(uint32_t*)(sm + SM_A_LO + o1) = pack_bf(v2 - h2, v3 - h3);
        }
    }
    load_w(sm, w2, tid);
    __syncthreads();

    gemm128(smb + SM_A_HI, smb + SM_A_LO, smb + SM_W_HI, smb + SM_W_LO,
            mbase, lane, acc);

    // epilogue 2: bias + LayerNorm + store g_h + fused column stats
    {
        const int g = lane >> 2, q = lane & 3;
        const int r0 = mbase + g, r1 = r0 + 8;
        float s0 = 0.f, q0 = 0.f, s1 = 0.f, q1 = 0.f;
#pragma unroll
        for (int nt = 0; nt < 16; nt++) {
            int c = nt * 8 + 2 * q;
            float bb0 = b2s[c], bb1 = b2s[c + 1];
            acc[nt][0] += bb0;
            acc[nt][1] += bb1;
            acc[nt][2] += bb0;
            acc[nt][3] += bb1;
            s0 += acc[nt][0] + acc[nt][1];
            q0 += acc[nt][0] * acc[nt][0] + acc[nt][1] * acc[nt][1];
            s1 += acc[nt][2] + acc[nt][3];
            q1 += acc[nt][2] * acc[nt][2] + acc[nt][3] * acc[nt][3];
        }
#pragma unroll
        for (int off = 1; off < 4; off <<= 1) {
            s0 += __shfl_xor_sync(0xffffffffu, s0, off);
            q0 += __shfl_xor_sync(0xffffffffu, q0, off);
            s1 += __shfl_xor_sync(0xffffffffu, s1, off);
            q1 += __shfl_xor_sync(0xffffffffu, q1, off);
        }
        const float invD = 1.f / D;
        float mu0 = s0 * invD, mu1 = s1 * invD;
        float rs0 = rsqrtf(q0 * invD - mu0 * mu0 + EPS);
        float rs1 = rsqrtf(q1 * invD - mu1 * mu1 + EPS);
        int gr0 = rowbase + r0, gr1 = rowbase + r1;
        bool ok0 = gr0 < N_NODES, ok1 = gr1 < N_NODES;
#pragma unroll
        for (int nt = 0; nt < 16; nt++) {
            int c = nt * 8 + 2 * q;
            float gg0 = gs[c], gg1 = gs[c + 1];
            float be0 = bs[c], be1 = bs[c + 1];
            float y00 = 0.f, y01 = 0.f, y10 = 0.f, y11 = 0.f;
            if (ok0) {
                y00 = fmaf((acc[nt][0] - mu0) * rs0, gg0, be0);
                y01 = fmaf((acc[nt][1] - mu0) * rs0, gg1, be1);
                *(float2*)(g_h + (size_t)gr0 * D + c) = make_float2(y00, y01);
            }
            if (ok1) {
                y10 = fmaf((acc[nt][2] - mu1) * rs1, gg0, be0);
                y11 = fmaf((acc[nt][3] - mu1) * rs1, gg1, be1);
                *(float2*)(g_h + (size_t)gr1 * D + c) = make_float2(y10, y11);
            }
            float sc = y00 + y10, sc1 = y01 + y11;
            float qc = y00 * y00 + y10 * y10, qc1 = y01 * y01 + y11 * y11;
#pragma unroll
            for (int off = 4; off < 32; off <<= 1) {
                sc += __shfl_xor_sync(0xffffffffu, sc, off);
                sc1 += __shfl_xor_sync(0xffffffffu, sc1, off);
                qc += __shfl_xor_sync(0xffffffffu, qc, off);
                qc1 += __shfl_xor_sync(0xffffffffu, qc1, off);
            }
            if (lane < 4) {
                atomicAdd(&s_cs[c], sc);
                atomicAdd(&s_cs[c + 1], sc1);
                atomicAdd(&s_cq[c], qc);
                atomicAdd(&s_cq[c + 1], qc1);
            }
        }
    }
    __syncthreads();
    if (tid < D) {
        atomicAdd(&g_colsum[tid], s_cs[tid]);
        atomicAdd(&g_colsq[tid], s_cq[tid]);
    }
}

// ---------------- K5: GraphNorm stats + apply + ReLU + residual -------------
__global__ void __launch_bounds__(256) final_kernel(
    const float* __restrict__ node, const float* __restrict__ gn_w,
    const float* __restrict__ gn_b, const float* __restrict__ gn_ms,
    float* __restrict__ out) {
    __shared__ float s_scale[D];
    __shared__ float s_shift[D];
    if (threadIdx.x < D) {
        int j = threadIdx.x;
        const float invN = 1.f / (float)N_NODES;
        float mu = g_colsum[j] * invN;
        float ex2 = g_colsq[j] * invN;
        float ms = gn_ms[j];
        float var = ex2 - 2.f * ms * mu * mu + ms * ms * mu * mu;
        float a = rsqrtf(var + EPS) * gn_w[j];
        s_scale[j] = a;
        s_shift[j] = gn_b[j] - ms * mu * a;
    }
    __syncthreads();
    int i = blockIdx.x * blockDim.x + threadIdx.x;
    const int tot4 = N_NODES * D / 4;
    if (i >= tot4) return;
    const float4* h4 = (const float4*)g_h;
    const float4* n4 = (const float4*)node;
    const float4* s4 = (const float4*)s_scale;
    const float4* t4 = (const float4*)s_shift;
    float4* o4 = (float4*)out;
    int c = i & 31;
    float4 h = h4[i], s = s4[c], t = t4[c], n = n4[i];
    float4 r;
    r.x = fmaxf(fmaf(h.x, s.x, t.x), 0.f) + n.x;
    r.y = fmaxf(fmaf(h.y, s.y, t.y), 0.f) + n.y;
    r.z = fmaxf(fmaf(h.z, s.z, t.z), 0.f) + n.z;
    r.w = fmaxf(fmaf(h.w, s.w, t.w), 0.f) + n.w;
    o4[i] = r;
}

// ---------------- launch ----------------
extern "C" void kernel_launch(void* const* d_in, const int* in_sizes, int n_in,
                              void* d_out, int out_size) {
    const float* node = (const float*)d_in[0];
    const float* edge = (const float*)d_in[1];
    const float* w1 = (const float*)d_in[2];
    const float* b1 = (const float*)d_in[3];
    const float* w2 = (const float*)d_in[4];
    const float* b2 = (const float*)d_in[5];
    const float* lng = (const float*)d_in[6];
    const float* lnb = (const float*)d_in[7];
    const float* gnw = (const float*)d_in[8];
    const float* gnb = (const float*)d_in[9];
    const float* gnms = (const float*)d_in[10];
    const void* ei = d_in[11];
    float* out = (float*)d_out;

    static int inited = 0;
    if (!inited) {
        inited = 1;
        cudaFuncSetAttribute(mlp_mma_kernel,
                             cudaFuncAttributeMaxDynamicSharedMemorySize,
                             MLP_SMEM_BYTES);
    }

    zero_kernel<<<(N_NODES + 255) / 256, 256>>>((const int*)ei);
    hist_kernel<<<(N_EDGES + 255) / 256, 256>>>(ei);
    scan_kernel<<<NB_SCAN, 1024>>>();
    fill_kernel<<<(N_EDGES + 255) / 256, 256>>>(ei);

    const int gather_blocks = (N_NODES * 32 + 255) / 256;
    gather_kernel<<<gather_blocks, 256>>>(node, edge);

    mlp_mma_kernel<<<N_TILES, 256, MLP_SMEM_BYTES>>>(w1, b1, w2, b2, lng, lnb);

    const int tot4 = N_NODES * D / 4;
    final_kernel<<<(tot4 + 255) / 256, 256>>>(node, gnw, gnb, gnms, out);
}